// round 15
// baseline (speedup 1.0000x reference)
#include <cuda_runtime.h>
#include <cuda_fp16.h>
#include <math.h>
#include <stdint.h>

#define BB 64      // batch
#define TT 512     // seq len
#define DD 512     // input size
#define HH 1024    // hidden size
#define GG 4096    // 4*H

// ---------------------------------------------------------------------------
// Global scratch
// ---------------------------------------------------------------------------
// xz permuted fp16: [dir][t][b][p]
__device__ __half g_xz[(size_t)2 * TT * BB * GG];
// Wh fp16 (hi only), B-fragment order: [dir][nt(512)][kc16(64)][lane(32)]
__device__ uint2 g_Wfrag[(size_t)2 * 512 * 64 * 32];
// Wx fp16 (hi only), B-fragment order: [dir][nt(512)][kc16(32)][lane(32)]
__device__ uint2 g_Wxfrag[(size_t)2 * 512 * 32 * 32];
__device__ float g_biasp[2 * GG];
// X fp16 (hi only): [m(32768)][k(512)]
__device__ __half g_Xh[(size_t)32768 * 512];
// h fp16 (hi only): [parity][dir][kc64(16)][b(64)][64 halfs = 128B]
__device__ __align__(16) char g_A[(size_t)2 * 2 * 16 * 64 * 128];
// distributed barrier: [dir(2)][counter(8)] padded 128B apart
__device__ unsigned g_bars[2 * 8 * 32];

#define A_PD ((size_t)16 * 64 * 128)   // 131072 B per (parity,dir)

// smem: A 16 chunks x (64 x 144B) = 147456, then sred 64KB, then sh
#define SM_SRED  147456
#define SM_SH    (SM_SRED + 65536)        // 212992
#define SM_TOTAL (SM_SH + 64 * 17 * 4)    // 217344

// ---------------------------------------------------------------------------
#define MMA16816(d, a0, a1, a2, a3, b0, b1)                                  \
    asm volatile(                                                            \
        "mma.sync.aligned.m16n8k16.row.col.f32.f16.f16.f32 "                 \
        "{%0,%1,%2,%3}, {%4,%5,%6,%7}, {%8,%9}, {%0,%1,%2,%3};"              \
        : "+f"((d)[0]), "+f"((d)[1]), "+f"((d)[2]), "+f"((d)[3])             \
        : "r"(a0), "r"(a1), "r"(a2), "r"(a3), "r"(b0), "r"(b1))

#define LDSM_X4(r0, r1, r2, r3, addr)                                        \
    asm volatile(                                                            \
        "ldmatrix.sync.aligned.m8n8.x4.shared.b16 {%0,%1,%2,%3}, [%4];"      \
        : "=r"(r0), "=r"(r1), "=r"(r2), "=r"(r3) : "r"(addr))

#define CP16(dst, src)                                                       \
    asm volatile("cp.async.cg.shared.global [%0], [%1], 16;"                 \
                 :: "r"(dst), "l"(src))

__device__ __forceinline__ uint32_t smem_u32(const void* p) {
    uint32_t a;
    asm("{ .reg .u64 t; cvta.to.shared.u64 t, %1; cvt.u32.u64 %0, t; }"
        : "=r"(a) : "l"(p));
    return a;
}

__device__ __forceinline__ float tanh_fast(float x) {
    float y;
    asm("tanh.approx.f32 %0, %1;" : "=f"(y) : "f"(x));
    return y;
}
__device__ __forceinline__ float sigmoid_fast(float x) {
    return fmaf(tanh_fast(0.5f * x), 0.5f, 0.5f);
}

// ---------------------------------------------------------------------------
__global__ void init_kernel() {
    int i = blockIdx.x * blockDim.x + threadIdx.x;   // 0..131071
    ((uint32_t*)g_A)[i] = 0u;
    if (i < 2 * 8 * 32) g_bars[i] = 0u;
}

// ---------------------------------------------------------------------------
__global__ void convX_kernel(const float* __restrict__ X) {
    size_t idx = (size_t)blockIdx.x * blockDim.x + threadIdx.x;
    float4 v = ((const float4*)X)[idx];
    __half h0 = __float2half_rn(v.x), h1 = __float2half_rn(v.y);
    __half h2 = __float2half_rn(v.z), h3 = __float2half_rn(v.w);
    uint2 hi;
    hi.x = (uint32_t)__half_as_ushort(h0) | ((uint32_t)__half_as_ushort(h1) << 16);
    hi.y = (uint32_t)__half_as_ushort(h2) | ((uint32_t)__half_as_ushort(h3) << 16);
    ((uint2*)g_Xh)[idx] = hi;
}

// ---------------------------------------------------------------------------
__global__ void convW_kernel(const float* __restrict__ Whf,
                             const float* __restrict__ Whb) {
    int idx = blockIdx.x * blockDim.x + threadIdx.x;
    int lane = idx & 31;
    int kc   = (idx >> 5) & 63;
    int nt   = (idx >> 11) & 511;
    int dir  = idx >> 20;
    const float* W = dir ? Whb : Whf;

    int p   = nt * 8 + (lane >> 2);
    int col = ((p & 3) << 10) + (p >> 2);
    int k0  = kc * 16 + (lane & 3) * 2;

    float w0 = W[(size_t)(k0)     * GG + col];
    float w1 = W[(size_t)(k0 + 1) * GG + col];
    float w2 = W[(size_t)(k0 + 8) * GG + col];
    float w3 = W[(size_t)(k0 + 9) * GG + col];

    uint2 hi;
    hi.x = (uint32_t)__half_as_ushort(__float2half_rn(w0)) |
           ((uint32_t)__half_as_ushort(__float2half_rn(w1)) << 16);
    hi.y = (uint32_t)__half_as_ushort(__float2half_rn(w2)) |
           ((uint32_t)__half_as_ushort(__float2half_rn(w3)) << 16);

    g_Wfrag[(((size_t)dir * 512 + nt) * 64 + kc) * 32 + lane] = hi;
}

// ---------------------------------------------------------------------------
__global__ void convWx_kernel(const float* __restrict__ Wxf,
                              const float* __restrict__ Wxb,
                              const float* __restrict__ bf,
                              const float* __restrict__ bb) {
    int idx = blockIdx.x * blockDim.x + threadIdx.x;
    int lane = idx & 31;
    int kc   = (idx >> 5) & 31;
    int nt   = (idx >> 10) & 511;
    int dir  = idx >> 19;
    const float* W = dir ? Wxb : Wxf;

    int p   = nt * 8 + (lane >> 2);
    int col = ((p & 3) << 10) + (p >> 2);
    int k0  = kc * 16 + (lane & 3) * 2;

    float w0 = W[(size_t)(k0)     * GG + col];
    float w1 = W[(size_t)(k0 + 1) * GG + col];
    float w2 = W[(size_t)(k0 + 8) * GG + col];
    float w3 = W[(size_t)(k0 + 9) * GG + col];

    uint2 hi;
    hi.x = (uint32_t)__half_as_ushort(__float2half_rn(w0)) |
           ((uint32_t)__half_as_ushort(__float2half_rn(w1)) << 16);
    hi.y = (uint32_t)__half_as_ushort(__float2half_rn(w2)) |
           ((uint32_t)__half_as_ushort(__float2half_rn(w3)) << 16);

    g_Wxfrag[(((size_t)dir * 512 + nt) * 32 + kc) * 32 + lane] = hi;

    if (kc == 0 && (lane & 3) == 0) {
        const float* bias = dir ? bb : bf;
        g_biasp[dir * GG + p] = bias[col];
    }
}

// ---------------------------------------------------------------------------
// Input projection: 1-term fp16 mma (X_hi @ W_hi); fp16 xz epilogue.
// ---------------------------------------------------------------------------
__global__ void __launch_bounds__(256, 1) proj_kernel() {
    __shared__ __align__(16) char sX[2 * 6144];

    const int dir = blockIdx.z;
    const int n0 = blockIdx.x * 128;
    const int m0 = blockIdx.y * 128;
    const int tid = threadIdx.x;
    const int warp = tid >> 5, lane = tid & 31;
    const int wm = warp >> 2, wn = warp & 3;
    const int qr = lane >> 2, qc = lane & 3;

    const uint2* WX = g_Wxfrag + (size_t)dir * 512 * 32 * 32;
    const int ntbase = (n0 >> 3) + wn * 4;

    const uint32_t sX0 = smem_u32(sX);

    auto stage = [&](int c) {
        const int row = tid >> 1, q = tid & 1;
        const char* src = (const char*)g_Xh +
                          (((size_t)(m0 + row) * 512 + c * 16) << 1) + q * 16;
        const uint32_t dst = sX0 + (c & 1) * 6144 + row * 48 + q * 16;
        CP16(dst, src);
    };

    float d[4][4][4] = {};

    stage(0);
    asm volatile("cp.async.commit_group;" ::: "memory");

    for (int c = 0; c < 32; c++) {
        __syncthreads();
        if (c < 31) {
            stage(c + 1);
            asm volatile("cp.async.commit_group;" ::: "memory");
            asm volatile("cp.async.wait_group 1;" ::: "memory");
        } else {
            asm volatile("cp.async.wait_group 0;" ::: "memory");
        }
        __syncthreads();

        uint2 bh[4];
#pragma unroll
        for (int nt = 0; nt < 4; nt++)
            bh[nt] = WX[(((size_t)(ntbase + nt)) * 32 + c) * 32 + lane];

        const uint32_t slot = sX0 + (c & 1) * 6144;
        const uint32_t lrow = (lane & 15) * 48 + ((lane >> 4) << 4);
#pragma unroll
        for (int mt = 0; mt < 4; mt++) {
            const uint32_t arow = slot + (wm * 64 + mt * 16) * 48 + lrow;
            uint32_t a0, a1, a2, a3;
            LDSM_X4(a0, a1, a2, a3, arow);
#pragma unroll
            for (int nt = 0; nt < 4; nt++)
                MMA16816(d[mt][nt], a0, a1, a2, a3, bh[nt].x, bh[nt].y);
        }
    }

#pragma unroll
    for (int mt = 0; mt < 4; mt++) {
#pragma unroll
        for (int nt = 0; nt < 4; nt++) {
            const int n = n0 + wn * 32 + nt * 8 + qc * 2;
            const float2 bv = *(const float2*)(g_biasp + dir * GG + n);
            const int ma = m0 + wm * 64 + mt * 16 + qr;
            const int mb = ma + 8;
            __half2 h0 = __floats2half2_rn(d[mt][nt][0] + bv.x, d[mt][nt][1] + bv.y);
            __half2 h1 = __floats2half2_rn(d[mt][nt][2] + bv.x, d[mt][nt][3] + bv.y);
            *(__half2*)(g_xz + (((size_t)dir * TT + (ma & 511)) * BB + (ma >> 9)) * GG + n) = h0;
            *(__half2*)(g_xz + (((size_t)dir * TT + (mb & 511)) * BB + (mb >> 9)) * GG + n) = h1;
        }
    }
}

// ---------------------------------------------------------------------------
// Persistent recurrence: grid (64,2), 512 threads = 4 ntw x 4 kh warps.
// W in registers; MUFU gates; distributed 8-way barrier counters per dir.
// ---------------------------------------------------------------------------
__global__ void __launch_bounds__(512, 1) lstm_kernel(float* __restrict__ out) {
    extern __shared__ char dsm[];
    const uint32_t sA0 = smem_u32(dsm);               // 16 chunks x 64 x 144B
    float* sred = (float*)(dsm + SM_SRED);            // [4kh][4ntw][32][32]
    float (*sh)[17] = (float(*)[17])(dsm + SM_SH);    // [64][17]

    const int dir  = blockIdx.y;
    const int nblk = blockIdx.x;                      // 0..63
    const int tid  = threadIdx.x;
    const int warp = tid >> 5;
    const int lane = tid & 31;
    const int ntw = warp & 3;                         // 0..3: 2 ntiles each
    const int kh  = warp >> 2;                        // 0..3: 4 chunks each
    const int qr = lane >> 2;
    const int qc = lane & 3;
    const int ntg0 = nblk * 8 + ntw * 2;

    const int u = qc >> 1;
    const bool odd = qc & 1;
    const int mt = kh;                                // epilogue row tile
    const int bq = mt * 16 + qr + (odd ? 8 : 0);      // epilogue batch row

    const int st_b = tid >> 3;
    const int st_q = tid & 7;

    // arrival counter for this CTA; poll set for this direction
    unsigned* my_ctr   = &g_bars[(dir * 8 + (nblk & 7)) * 32];
    unsigned* poll_ctr = &g_bars[(dir * 8 + (tid & 7)) * 32];

    // ---- hoist this warp's W fragments into registers (loop-invariant) ----
    uint2 wreg[2][16];
    {
        const uint2* Bh = g_Wfrag + (((size_t)dir * 512 + ntg0) * 64) * 32 + lane;
#pragma unroll
        for (int nq = 0; nq < 2; nq++)
#pragma unroll
            for (int i = 0; i < 16; i++)
                wreg[nq][i] = Bh[((size_t)nq * 64 + kh * 16 + i) * 32];
    }

    float cv[2] = {0.0f, 0.0f};

    uint2 xv[2];
    {
        const int t0 = dir ? (TT - 1) : 0;
        const __half* xz = g_xz + ((size_t)dir * TT + t0) * BB * GG;
#pragma unroll
        for (int q = 0; q < 2; q++) {
            const int jq = nblk * 16 + (ntw * 2 + q) * 2 + u;
            xv[q] = *(const uint2*)(xz + (size_t)bq * GG + jq * 4);
        }
    }

    for (int s = 0; s < TT; s++) {
        const int t  = dir ? (TT - 1 - s) : s;
        const int pr = s & 1;
        const int pw = pr ^ 1;
        const char* srcA = g_A + (size_t)(pr * 2 + dir) * A_PD;

        // ---- stage all 16 chunks in 2 groups (group g: chunks bit1==g) ----
#pragma unroll
        for (int g = 0; g < 2; g++) {
#pragma unroll
            for (int ci = 0; ci < 8; ci++) {
                const int chunk = ((ci >> 1) << 2) | (g << 1) | (ci & 1);
                const char* src = srcA + (size_t)chunk * 8192 + st_b * 128 + st_q * 16;
                const uint32_t dst = sA0 + chunk * 9216 + st_b * 144 + st_q * 16;
                CP16(dst, src);
            }
            asm volatile("cp.async.commit_group;" ::: "memory");
        }

        float d[4][2][4] = {};

        // ---- compute: 2 phases x 2 chunks x 4 ksteps, 2 nt per A frag ----
#pragma unroll
        for (int phase = 0; phase < 2; phase++) {
            if (phase == 0) {
                asm volatile("cp.async.wait_group 1;" ::: "memory");
            } else {
                asm volatile("cp.async.wait_group 0;" ::: "memory");
            }
            __syncthreads();

#pragma unroll
            for (int cc = 0; cc < 2; cc++) {
                const int lc = phase * 2 + cc;        // local chunk 0..3
                const int chunk = kh * 4 + lc;
                const uint32_t slot = sA0 + chunk * 9216;
                const uint32_t lrow = (lane & 15) * 144 + ((lane >> 4) << 4);
#pragma unroll
                for (int sub = 0; sub < 4; sub++) {
                    const uint32_t arow = slot + sub * 32 + lrow;
                    const uint2 w0 = wreg[0][lc * 4 + sub];
                    const uint2 w1 = wreg[1][lc * 4 + sub];
#pragma unroll
                    for (int m = 0; m < 4; m++) {
                        uint32_t a0, a1, a2, a3;
                        LDSM_X4(a0, a1, a2, a3, arow + m * 2304);
                        MMA16816(d[m][0], a0, a1, a2, a3, w0.x, w0.y);
                        MMA16816(d[m][1], a0, a1, a2, a3, w1.x, w1.y);
                    }
                }
            }
        }

        // ---- export partials for the 3 non-owned mt tiles ----
        {
            const int wbase = (kh * 4 + ntw) * 1024;
#pragma unroll
            for (int m = 0; m < 4; m++) {
                if (m == kh) continue;
#pragma unroll
                for (int nq = 0; nq < 2; nq++)
#pragma unroll
                    for (int e = 0; e < 4; e++)
                        sred[wbase + (m * 8 + nq * 4 + e) * 32 + lane] = d[m][nq][e];
            }
        }
        __syncthreads();

        // ---- reduce + gate math: warp (ntw,kh) owns mt=kh, its 2 ntiles ----
        {
#pragma unroll
            for (int q = 0; q < 2; q++) {
                float z0 = d[mt][q][0], z1 = d[mt][q][1];
                float z2 = d[mt][q][2], z3 = d[mt][q][3];
#pragma unroll
                for (int src = 0; src < 4; src++) {
                    if (src == kh) continue;
                    const int rb = (src * 4 + ntw) * 1024 + (mt * 8 + q * 4) * 32 + lane;
                    z0 += sred[rb];
                    z1 += sred[rb + 32];
                    z2 += sred[rb + 64];
                    z3 += sred[rb + 96];
                }
                float e0 = __shfl_xor_sync(0xffffffffu, z0, 1);
                float e1 = __shfl_xor_sync(0xffffffffu, z1, 1);
                float e2 = __shfl_xor_sync(0xffffffffu, z2, 1);
                float e3 = __shfl_xor_sync(0xffffffffu, z3, 1);

                float zi = odd ? e2 : z0;
                float zf = odd ? e3 : z1;
                float zo = odd ? z2 : e0;
                float zg = odd ? z3 : e1;

                const float2 x01 = __half22float2(*(const __half2*)&xv[q].x);
                const float2 x23 = __half22float2(*(const __half2*)&xv[q].y);
                zi += x01.x; zf += x01.y; zo += x23.x; zg += x23.y;

                const float ig = sigmoid_fast(zi);
                const float fg = sigmoid_fast(zf);
                const float og = sigmoid_fast(zo);
                const float gt = tanh_fast(zg);

                const float cn = fg * cv[q] + ig * gt;
                const float hn = og * tanh_fast(cn);
                cv[q] = cn;
                sh[bq][(ntw * 2 + q) * 2 + u] = hn;
            }
        }
        __syncthreads();

        // ---- write h_hi (fp16) for next step, parity pw ----
        if (tid < 64) {
            const int b = tid;
            char* dst = g_A + (size_t)(pw * 2 + dir) * A_PD +
                        (size_t)(nblk >> 2) * 8192 + (size_t)b * 128 + (nblk & 3) * 32;
            __half tmp[16];
#pragma unroll
            for (int q = 0; q < 16; q++) tmp[q] = __float2half_rn(sh[b][q]);
            *(uint4*)(dst)      = *(uint4*)(tmp);
            *(uint4*)(dst + 16) = *(uint4*)(tmp + 8);
        }

        // ---- out store (reads sh): overlapped with barrier spin below ----
        auto store_out = [&]() {
            const int b = tid >> 3;
            const int e = tid & 7;
            float2 v;
            v.x = sh[b][e * 2];
            v.y = sh[b][e * 2 + 1];
            *(float2*)(out + (((size_t)b * TT + t) * 2 + dir) * HH +
                       nblk * 16 + e * 2) = v;
        };

        if (s < TT - 1) {
            __syncthreads();   // h-write visible CTA-wide before arrive
            if (tid == 0) {
                asm volatile("red.release.gpu.global.add.u32 [%0], 1;"
                             :: "l"(my_ctr) : "memory");
            }
            store_out();       // overlap with spin
            {
                const int tn = dir ? (TT - 2 - s) : (s + 1);
                const __half* xz = g_xz + ((size_t)dir * TT + tn) * BB * GG;
#pragma unroll
                for (int q = 0; q < 2; q++) {
                    const int jq = nblk * 16 + (ntw * 2 + q) * 2 + u;
                    xv[q] = *(const uint2*)(xz + (size_t)bq * GG + jq * 4);
                }
            }
            if (tid < 8) {     // 8 pollers, one counter each
                const unsigned target = 8u * (unsigned)(s + 1);
                unsigned v;
                do {
                    asm volatile("ld.acquire.gpu.global.u32 %0, [%1];"
                                 : "=r"(v) : "l"(poll_ctr) : "memory");
                } while (v < target);
            }
            __syncthreads();
        } else {
            store_out();
        }
    }
}

// ---------------------------------------------------------------------------
extern "C" void kernel_launch(void* const* d_in, const int* in_sizes, int n_in,
                              void* d_out, int out_size) {
    const float* X    = (const float*)d_in[0];
    const float* Wx_f = (const float*)d_in[1];
    const float* Wh_f = (const float*)d_in[2];
    const float* b_f  = (const float*)d_in[3];
    const float* Wx_b = (const float*)d_in[4];
    const float* Wh_b = (const float*)d_in[5];
    const float* b_b  = (const float*)d_in[6];
    float* out = (float*)d_out;

    cudaFuncSetAttribute(lstm_kernel,
                         cudaFuncAttributeMaxDynamicSharedMemorySize, SM_TOTAL);

    init_kernel<<<512, 256>>>();
    convX_kernel<<<16384, 256>>>(X);
    convW_kernel<<<8192, 256>>>(Wh_f, Wh_b);
    convWx_kernel<<<4096, 256>>>(Wx_f, Wx_b, b_f, b_b);

    proj_kernel<<<dim3(32, 256, 2), 256>>>();

    lstm_kernel<<<dim3(64, 2), 512, SM_TOTAL>>>(out);
}

// round 16
// speedup vs baseline: 1.0410x; 1.0410x over previous
#include <cuda_runtime.h>
#include <cuda_fp16.h>
#include <math.h>
#include <stdint.h>

#define BB 64      // batch
#define TT 512     // seq len
#define DD 512     // input size
#define HH 1024    // hidden size
#define GG 4096    // 4*H

// ---------------------------------------------------------------------------
// Global scratch
// ---------------------------------------------------------------------------
// xz permuted fp16: [dir][t][b][p]
__device__ __half g_xz[(size_t)2 * TT * BB * GG];
// Wh fp16 (hi only), B-fragment order: [dir][nt(512)][kc16(64)][lane(32)]
__device__ uint2 g_Wfrag[(size_t)2 * 512 * 64 * 32];
// Wx fp16 (hi only), B-fragment order: [dir][nt(512)][kc16(32)][lane(32)]
__device__ uint2 g_Wxfrag[(size_t)2 * 512 * 32 * 32];
__device__ float g_biasp[2 * GG];
// X fp16 (hi only): [m(32768)][k(512)]
__device__ __half g_Xh[(size_t)32768 * 512];
// h fp16 (hi only): [parity][dir][kc64(16)][b(64)][64 halfs = 128B]
__device__ __align__(16) char g_A[(size_t)2 * 2 * 16 * 64 * 128];
__device__ unsigned g_barrier2[2];   // per-direction barrier counters

#define A_PD ((size_t)16 * 64 * 128)   // 131072 B per (parity,dir)

// smem: A 16 chunks x (64 x 144B) = 147456, then sred 64KB, then sh
#define SM_SRED  147456
#define SM_SH    (SM_SRED + 65536)        // 212992
#define SM_TOTAL (SM_SH + 64 * 17 * 4)    // 217344

// ---------------------------------------------------------------------------
#define MMA16816(d, a0, a1, a2, a3, b0, b1)                                  \
    asm volatile(                                                            \
        "mma.sync.aligned.m16n8k16.row.col.f32.f16.f16.f32 "                 \
        "{%0,%1,%2,%3}, {%4,%5,%6,%7}, {%8,%9}, {%0,%1,%2,%3};"              \
        : "+f"((d)[0]), "+f"((d)[1]), "+f"((d)[2]), "+f"((d)[3])             \
        : "r"(a0), "r"(a1), "r"(a2), "r"(a3), "r"(b0), "r"(b1))

#define LDSM_X4(r0, r1, r2, r3, addr)                                        \
    asm volatile(                                                            \
        "ldmatrix.sync.aligned.m8n8.x4.shared.b16 {%0,%1,%2,%3}, [%4];"      \
        : "=r"(r0), "=r"(r1), "=r"(r2), "=r"(r3) : "r"(addr))

#define CP16(dst, src)                                                       \
    asm volatile("cp.async.cg.shared.global [%0], [%1], 16;"                 \
                 :: "r"(dst), "l"(src))

__device__ __forceinline__ uint32_t smem_u32(const void* p) {
    uint32_t a;
    asm("{ .reg .u64 t; cvta.to.shared.u64 t, %1; cvt.u32.u64 %0, t; }"
        : "=r"(a) : "l"(p));
    return a;
}

__device__ __forceinline__ float tanh_fast(float x) {
    float y;
    asm("tanh.approx.f32 %0, %1;" : "=f"(y) : "f"(x));
    return y;
}
__device__ __forceinline__ float sigmoid_fast(float x) {
    return fmaf(tanh_fast(0.5f * x), 0.5f, 0.5f);
}

// ---------------------------------------------------------------------------
__global__ void init_kernel() {
    int i = blockIdx.x * blockDim.x + threadIdx.x;   // 0..131071
    ((uint32_t*)g_A)[i] = 0u;
    if (i < 2) g_barrier2[i] = 0u;
}

// ---------------------------------------------------------------------------
__global__ void convX_kernel(const float* __restrict__ X) {
    size_t idx = (size_t)blockIdx.x * blockDim.x + threadIdx.x;
    float4 v = ((const float4*)X)[idx];
    __half h0 = __float2half_rn(v.x), h1 = __float2half_rn(v.y);
    __half h2 = __float2half_rn(v.z), h3 = __float2half_rn(v.w);
    uint2 hi;
    hi.x = (uint32_t)__half_as_ushort(h0) | ((uint32_t)__half_as_ushort(h1) << 16);
    hi.y = (uint32_t)__half_as_ushort(h2) | ((uint32_t)__half_as_ushort(h3) << 16);
    ((uint2*)g_Xh)[idx] = hi;
}

// ---------------------------------------------------------------------------
__global__ void convW_kernel(const float* __restrict__ Whf,
                             const float* __restrict__ Whb) {
    int idx = blockIdx.x * blockDim.x + threadIdx.x;
    int lane = idx & 31;
    int kc   = (idx >> 5) & 63;
    int nt   = (idx >> 11) & 511;
    int dir  = idx >> 20;
    const float* W = dir ? Whb : Whf;

    int p   = nt * 8 + (lane >> 2);
    int col = ((p & 3) << 10) + (p >> 2);
    int k0  = kc * 16 + (lane & 3) * 2;

    float w0 = W[(size_t)(k0)     * GG + col];
    float w1 = W[(size_t)(k0 + 1) * GG + col];
    float w2 = W[(size_t)(k0 + 8) * GG + col];
    float w3 = W[(size_t)(k0 + 9) * GG + col];

    uint2 hi;
    hi.x = (uint32_t)__half_as_ushort(__float2half_rn(w0)) |
           ((uint32_t)__half_as_ushort(__float2half_rn(w1)) << 16);
    hi.y = (uint32_t)__half_as_ushort(__float2half_rn(w2)) |
           ((uint32_t)__half_as_ushort(__float2half_rn(w3)) << 16);

    g_Wfrag[(((size_t)dir * 512 + nt) * 64 + kc) * 32 + lane] = hi;
}

// ---------------------------------------------------------------------------
__global__ void convWx_kernel(const float* __restrict__ Wxf,
                              const float* __restrict__ Wxb,
                              const float* __restrict__ bf,
                              const float* __restrict__ bb) {
    int idx = blockIdx.x * blockDim.x + threadIdx.x;
    int lane = idx & 31;
    int kc   = (idx >> 5) & 31;
    int nt   = (idx >> 10) & 511;
    int dir  = idx >> 19;
    const float* W = dir ? Wxb : Wxf;

    int p   = nt * 8 + (lane >> 2);
    int col = ((p & 3) << 10) + (p >> 2);
    int k0  = kc * 16 + (lane & 3) * 2;

    float w0 = W[(size_t)(k0)     * GG + col];
    float w1 = W[(size_t)(k0 + 1) * GG + col];
    float w2 = W[(size_t)(k0 + 8) * GG + col];
    float w3 = W[(size_t)(k0 + 9) * GG + col];

    uint2 hi;
    hi.x = (uint32_t)__half_as_ushort(__float2half_rn(w0)) |
           ((uint32_t)__half_as_ushort(__float2half_rn(w1)) << 16);
    hi.y = (uint32_t)__half_as_ushort(__float2half_rn(w2)) |
           ((uint32_t)__half_as_ushort(__float2half_rn(w3)) << 16);

    g_Wxfrag[(((size_t)dir * 512 + nt) * 32 + kc) * 32 + lane] = hi;

    if (kc == 0 && (lane & 3) == 0) {
        const float* bias = dir ? bb : bf;
        g_biasp[dir * GG + p] = bias[col];
    }
}

// ---------------------------------------------------------------------------
// Input projection: 1-term fp16 mma (X_hi @ W_hi); fp16 xz epilogue.
// ---------------------------------------------------------------------------
__global__ void __launch_bounds__(256, 1) proj_kernel() {
    __shared__ __align__(16) char sX[2 * 6144];

    const int dir = blockIdx.z;
    const int n0 = blockIdx.x * 128;
    const int m0 = blockIdx.y * 128;
    const int tid = threadIdx.x;
    const int warp = tid >> 5, lane = tid & 31;
    const int wm = warp >> 2, wn = warp & 3;
    const int qr = lane >> 2, qc = lane & 3;

    const uint2* WX = g_Wxfrag + (size_t)dir * 512 * 32 * 32;
    const int ntbase = (n0 >> 3) + wn * 4;

    const uint32_t sX0 = smem_u32(sX);

    auto stage = [&](int c) {
        const int row = tid >> 1, q = tid & 1;
        const char* src = (const char*)g_Xh +
                          (((size_t)(m0 + row) * 512 + c * 16) << 1) + q * 16;
        const uint32_t dst = sX0 + (c & 1) * 6144 + row * 48 + q * 16;
        CP16(dst, src);
    };

    float d[4][4][4] = {};

    stage(0);
    asm volatile("cp.async.commit_group;" ::: "memory");

    for (int c = 0; c < 32; c++) {
        __syncthreads();
        if (c < 31) {
            stage(c + 1);
            asm volatile("cp.async.commit_group;" ::: "memory");
            asm volatile("cp.async.wait_group 1;" ::: "memory");
        } else {
            asm volatile("cp.async.wait_group 0;" ::: "memory");
        }
        __syncthreads();

        uint2 bh[4];
#pragma unroll
        for (int nt = 0; nt < 4; nt++)
            bh[nt] = WX[(((size_t)(ntbase + nt)) * 32 + c) * 32 + lane];

        const uint32_t slot = sX0 + (c & 1) * 6144;
        const uint32_t lrow = (lane & 15) * 48 + ((lane >> 4) << 4);
#pragma unroll
        for (int mt = 0; mt < 4; mt++) {
            const uint32_t arow = slot + (wm * 64 + mt * 16) * 48 + lrow;
            uint32_t a0, a1, a2, a3;
            LDSM_X4(a0, a1, a2, a3, arow);
#pragma unroll
            for (int nt = 0; nt < 4; nt++)
                MMA16816(d[mt][nt], a0, a1, a2, a3, bh[nt].x, bh[nt].y);
        }
    }

#pragma unroll
    for (int mt = 0; mt < 4; mt++) {
#pragma unroll
        for (int nt = 0; nt < 4; nt++) {
            const int n = n0 + wn * 32 + nt * 8 + qc * 2;
            const float2 bv = *(const float2*)(g_biasp + dir * GG + n);
            const int ma = m0 + wm * 64 + mt * 16 + qr;
            const int mb = ma + 8;
            __half2 h0 = __floats2half2_rn(d[mt][nt][0] + bv.x, d[mt][nt][1] + bv.y);
            __half2 h1 = __floats2half2_rn(d[mt][nt][2] + bv.x, d[mt][nt][3] + bv.y);
            *(__half2*)(g_xz + (((size_t)dir * TT + (ma & 511)) * BB + (ma >> 9)) * GG + n) = h0;
            *(__half2*)(g_xz + (((size_t)dir * TT + (mb & 511)) * BB + (mb >> 9)) * GG + n) = h1;
        }
    }
}

// ---------------------------------------------------------------------------
// Persistent recurrence: grid (64,2), 512 threads = 4 ntw x 4 kh warps.
// W in registers; MUFU gates; single-counter-per-dir barrier (R14-proven);
// single-shot A staging (one commit group, one wait, one bar).
// ---------------------------------------------------------------------------
__global__ void __launch_bounds__(512, 1) lstm_kernel(float* __restrict__ out) {
    extern __shared__ char dsm[];
    const uint32_t sA0 = smem_u32(dsm);               // 16 chunks x 64 x 144B
    float* sred = (float*)(dsm + SM_SRED);            // [4kh][4ntw][32][32]
    float (*sh)[17] = (float(*)[17])(dsm + SM_SH);    // [64][17]

    const int dir  = blockIdx.y;
    const int nblk = blockIdx.x;                      // 0..63
    const int tid  = threadIdx.x;
    const int warp = tid >> 5;
    const int lane = tid & 31;
    const int ntw = warp & 3;                         // 0..3: 2 ntiles each
    const int kh  = warp >> 2;                        // 0..3: 4 chunks each
    const int qr = lane >> 2;
    const int qc = lane & 3;
    const int ntg0 = nblk * 8 + ntw * 2;

    const int u = qc >> 1;
    const bool odd = qc & 1;
    const int mt = kh;                                // epilogue row tile
    const int bq = mt * 16 + qr + (odd ? 8 : 0);      // epilogue batch row

    const int st_b = tid >> 3;
    const int st_q = tid & 7;

    // ---- hoist this warp's W fragments into registers (loop-invariant) ----
    uint2 wreg[2][16];
    {
        const uint2* Bh = g_Wfrag + (((size_t)dir * 512 + ntg0) * 64) * 32 + lane;
#pragma unroll
        for (int nq = 0; nq < 2; nq++)
#pragma unroll
            for (int i = 0; i < 16; i++)
                wreg[nq][i] = Bh[((size_t)nq * 64 + kh * 16 + i) * 32];
    }

    float cv[2] = {0.0f, 0.0f};

    uint2 xv[2];
    {
        const int t0 = dir ? (TT - 1) : 0;
        const __half* xz = g_xz + ((size_t)dir * TT + t0) * BB * GG;
#pragma unroll
        for (int q = 0; q < 2; q++) {
            const int jq = nblk * 16 + (ntw * 2 + q) * 2 + u;
            xv[q] = *(const uint2*)(xz + (size_t)bq * GG + jq * 4);
        }
    }

    for (int s = 0; s < TT; s++) {
        const int t  = dir ? (TT - 1 - s) : s;
        const int pr = s & 1;
        const int pw = pr ^ 1;
        const char* srcA = g_A + (size_t)(pr * 2 + dir) * A_PD;

        // ---- stage all 16 chunks in ONE group: max MLP, single wait ----
#pragma unroll
        for (int ci = 0; ci < 16; ci++) {
            const char* src = srcA + (size_t)ci * 8192 + st_b * 128 + st_q * 16;
            const uint32_t dst = sA0 + ci * 9216 + st_b * 144 + st_q * 16;
            CP16(dst, src);
        }
        asm volatile("cp.async.commit_group;" ::: "memory");

        float d[4][2][4] = {};

        asm volatile("cp.async.wait_group 0;" ::: "memory");
        __syncthreads();

        // ---- compute: 4 local chunks x 4 ksteps, 2 nt per A frag ----
#pragma unroll
        for (int lc = 0; lc < 4; lc++) {
            const int chunk = kh * 4 + lc;
            const uint32_t slot = sA0 + chunk * 9216;
            const uint32_t lrow = (lane & 15) * 144 + ((lane >> 4) << 4);
#pragma unroll
            for (int sub = 0; sub < 4; sub++) {
                const uint32_t arow = slot + sub * 32 + lrow;
                const uint2 w0 = wreg[0][lc * 4 + sub];
                const uint2 w1 = wreg[1][lc * 4 + sub];
#pragma unroll
                for (int m = 0; m < 4; m++) {
                    uint32_t a0, a1, a2, a3;
                    LDSM_X4(a0, a1, a2, a3, arow + m * 2304);
                    MMA16816(d[m][0], a0, a1, a2, a3, w0.x, w0.y);
                    MMA16816(d[m][1], a0, a1, a2, a3, w1.x, w1.y);
                }
            }
        }

        // ---- export partials for the 3 non-owned mt tiles ----
        {
            const int wbase = (kh * 4 + ntw) * 1024;
#pragma unroll
            for (int m = 0; m < 4; m++) {
                if (m == kh) continue;
#pragma unroll
                for (int nq = 0; nq < 2; nq++)
#pragma unroll
                    for (int e = 0; e < 4; e++)
                        sred[wbase + (m * 8 + nq * 4 + e) * 32 + lane] = d[m][nq][e];
            }
        }
        __syncthreads();

        // ---- reduce + gate math: warp (ntw,kh) owns mt=kh, its 2 ntiles ----
        {
#pragma unroll
            for (int q = 0; q < 2; q++) {
                float z0 = d[mt][q][0], z1 = d[mt][q][1];
                float z2 = d[mt][q][2], z3 = d[mt][q][3];
#pragma unroll
                for (int src = 0; src < 4; src++) {
                    if (src == kh) continue;
                    const int rb = (src * 4 + ntw) * 1024 + (mt * 8 + q * 4) * 32 + lane;
                    z0 += sred[rb];
                    z1 += sred[rb + 32];
                    z2 += sred[rb + 64];
                    z3 += sred[rb + 96];
                }
                float e0 = __shfl_xor_sync(0xffffffffu, z0, 1);
                float e1 = __shfl_xor_sync(0xffffffffu, z1, 1);
                float e2 = __shfl_xor_sync(0xffffffffu, z2, 1);
                float e3 = __shfl_xor_sync(0xffffffffu, z3, 1);

                float zi = odd ? e2 : z0;
                float zf = odd ? e3 : z1;
                float zo = odd ? z2 : e0;
                float zg = odd ? z3 : e1;

                const float2 x01 = __half22float2(*(const __half2*)&xv[q].x);
                const float2 x23 = __half22float2(*(const __half2*)&xv[q].y);
                zi += x01.x; zf += x01.y; zo += x23.x; zg += x23.y;

                const float ig = sigmoid_fast(zi);
                const float fg = sigmoid_fast(zf);
                const float og = sigmoid_fast(zo);
                const float gt = tanh_fast(zg);

                const float cn = fg * cv[q] + ig * gt;
                const float hn = og * tanh_fast(cn);
                cv[q] = cn;
                sh[bq][(ntw * 2 + q) * 2 + u] = hn;
            }
        }
        __syncthreads();

        // ---- write h_hi (fp16) for next step, parity pw ----
        if (tid < 64) {
            const int b = tid;
            char* dst = g_A + (size_t)(pw * 2 + dir) * A_PD +
                        (size_t)(nblk >> 2) * 8192 + (size_t)b * 128 + (nblk & 3) * 32;
            __half tmp[16];
#pragma unroll
            for (int q = 0; q < 16; q++) tmp[q] = __float2half_rn(sh[b][q]);
            *(uint4*)(dst)      = *(uint4*)(tmp);
            *(uint4*)(dst + 16) = *(uint4*)(tmp + 8);
        }

        // ---- out store (reads sh): overlapped with barrier spin below ----
        auto store_out = [&]() {
            const int b = tid >> 3;
            const int e = tid & 7;
            float2 v;
            v.x = sh[b][e * 2];
            v.y = sh[b][e * 2 + 1];
            *(float2*)(out + (((size_t)b * TT + t) * 2 + dir) * HH +
                       nblk * 16 + e * 2) = v;
        };

        if (s < TT - 1) {
            __syncthreads();   // h-write visible CTA-wide before arrive
            if (tid == 0) {
                asm volatile("red.release.gpu.global.add.u32 [%0], 1;"
                             :: "l"(&g_barrier2[dir]) : "memory");
            }
            store_out();       // overlap with spin
            {
                const int tn = dir ? (TT - 2 - s) : (s + 1);
                const __half* xz = g_xz + ((size_t)dir * TT + tn) * BB * GG;
#pragma unroll
                for (int q = 0; q < 2; q++) {
                    const int jq = nblk * 16 + (ntw * 2 + q) * 2 + u;
                    xv[q] = *(const uint2*)(xz + (size_t)bq * GG + jq * 4);
                }
            }
            if (tid == 0) {
                const unsigned target = 64u * (unsigned)(s + 1);
                unsigned v;
                do {
                    asm volatile("ld.acquire.gpu.global.u32 %0, [%1];"
                                 : "=r"(v) : "l"(&g_barrier2[dir]) : "memory");
                } while (v < target);
            }
            __syncthreads();
        } else {
            store_out();
        }
    }
}

// ---------------------------------------------------------------------------
extern "C" void kernel_launch(void* const* d_in, const int* in_sizes, int n_in,
                              void* d_out, int out_size) {
    const float* X    = (const float*)d_in[0];
    const float* Wx_f = (const float*)d_in[1];
    const float* Wh_f = (const float*)d_in[2];
    const float* b_f  = (const float*)d_in[3];
    const float* Wx_b = (const float*)d_in[4];
    const float* Wh_b = (const float*)d_in[5];
    const float* b_b  = (const float*)d_in[6];
    float* out = (float*)d_out;

    cudaFuncSetAttribute(lstm_kernel,
                         cudaFuncAttributeMaxDynamicSharedMemorySize, SM_TOTAL);

    init_kernel<<<512, 256>>>();
    convX_kernel<<<16384, 256>>>(X);
    convW_kernel<<<8192, 256>>>(Wh_f, Wh_b);
    convWx_kernel<<<4096, 256>>>(Wx_f, Wx_b, b_f, b_b);

    proj_kernel<<<dim3(32, 256, 2), 256>>>();

    lstm_kernel<<<dim3(64, 2), 512, SM_TOTAL>>>(out);
}